// round 13
// baseline (speedup 1.0000x reference)
#include <cuda_runtime.h>
#include <cstdint>

#define BB 64
#define LL 1024
#define SS 8
#define DD 128
#define BL (BB*LL)          // 65536
#define NELEM (2*BL)        // 131072 element-sides
#define KEYSPACE 16384      // id*8 + (snap-1), id < 2000 -> key < 16000

// ---- device scratch ----
__device__ uint32_t g_cnt[NELEM];      // packed: cx | cy<<11 | s<<22
__device__ float4   g_hot[128*32];     // hot joint table (s<8, cx<4, cy<4), 64KB

// ============================================================
// Direct evaluation of one output row for (s, cx, cy).
// Warp-collective; lane holds float4 covering d' = 4*lane .. 4*lane+3.
// UNROLL: compile-time unroll factor for the enc loop (reg/MLP tradeoff).
// ============================================================
template <int UNROLL>
__device__ __forceinline__ float4 elem_eval(int s, int cx, int cy, int lane,
                              const float* __restrict__ aw1,
                              const float* __restrict__ ab1,
                              const float* __restrict__ aw2,
                              const float* __restrict__ ab2,
                              const float* __restrict__ ew1,
                              const float* __restrict__ eb1,
                              const float* __restrict__ ew2,
                              const float* __restrict__ eb2) {
    float fx = (float)cx, fy = (float)cy;
    float a0 = 0.f, a1 = 0.f;
#pragma unroll
    for (int m = 0; m < 4; ++m) {
        int d = lane + 32*m;
        float w = __ldg(&aw1[s*DD + d]);
        float b = __ldg(&ab1[d]);
        float h = fmaxf(fmaf(fx, w, b), 0.f) + fmaxf(fmaf(fy, w, b), 0.f);
        a0 = fmaf(h, __ldg(&aw2[2*d + 0]), a0);
        a1 = fmaf(h, __ldg(&aw2[2*d + 1]), a1);
    }
#pragma unroll
    for (int off = 16; off; off >>= 1) {
        a0 += __shfl_xor_sync(0xffffffffu, a0, off);
        a1 += __shfl_xor_sync(0xffffffffu, a1, off);
    }
    float y0 = fmaf(0.5f, a0, __ldg(&ab2[0]));
    float y1 = fmaf(0.5f, a1, __ldg(&ab2[1]));

    float4 e2 = __ldg(&((const float4*)eb2)[lane]);
    float4 acc;
    acc.x = 2.f*e2.x; acc.y = 2.f*e2.y; acc.z = 2.f*e2.z; acc.w = 2.f*e2.w;
    const float4* W2 = (const float4*)ew2;
#pragma unroll UNROLL
    for (int d = 0; d < DD; ++d) {
        float w = __ldg(&ew1[d]);
        float b = __ldg(&eb1[d]);
        float h = fmaxf(fmaf(y0, w, b), 0.f) + fmaxf(fmaf(y1, w, b), 0.f);
        float4 w2 = __ldg(&W2[d*32 + lane]);
        acc.x = fmaf(h, w2.x, acc.x);
        acc.y = fmaf(h, w2.y, acc.y);
        acc.z = fmaf(h, w2.z, acc.z);
        acc.w = fmaf(h, w2.w, acc.w);
    }
    return acc;
}

// Rare-path wrapper: noinline keeps registers out of the hot gather kernel.
__device__ __noinline__ float4 elem_direct(int s, int cx, int cy, int lane,
                              const float* __restrict__ aw1,
                              const float* __restrict__ ab1,
                              const float* __restrict__ aw2,
                              const float* __restrict__ ab2,
                              const float* __restrict__ ew1,
                              const float* __restrict__ eb1,
                              const float* __restrict__ ew2,
                              const float* __restrict__ eb2) {
    return elem_eval<4>(s, cx, cy, lane, aw1, ab1, aw2, ab2, ew1, eb1, ew2, eb2);
}

// ============================================================
// Fused kernel. Block roles by blockIdx.x:
//   [0,64)  : per-batch histogram count (64KB smem)
//   [64,68) : hot joint table, one row per warp (deep-unroll eval)
// ============================================================
__global__ __launch_bounds__(1024, 1)
void k_fused(const int* __restrict__ sid, const int* __restrict__ did,
             const int* __restrict__ ssn, const int* __restrict__ dsn,
             const float* __restrict__ aw1, const float* __restrict__ ab1,
             const float* __restrict__ aw2, const float* __restrict__ ab2,
             const float* __restrict__ ew1, const float* __restrict__ eb1,
             const float* __restrict__ ew2, const float* __restrict__ eb2) {
    extern __shared__ uint32_t smraw[];
    int bid = blockIdx.x;
    int tid = threadIdx.x;

    if (bid < 64) {
        // ---------------- count section ----------------
        uint32_t* tabS = smraw;                // KEYSPACE/2 words
        uint32_t* tabD = smraw + KEYSPACE/2;
        int b = bid;
        uint4* z = (uint4*)smraw;
#pragma unroll
        for (int i = 0; i < 4; ++i) z[tid + i*1024] = make_uint4(0,0,0,0);
        __syncthreads();

        int i = b*LL + tid;
        unsigned k1 = (unsigned)(sid[i]*8 + (ssn[i]-1));
        unsigned k2 = (unsigned)(did[i]*8 + (dsn[i]-1));
        k1 = min(k1, (unsigned)(KEYSPACE-1));
        k2 = min(k2, (unsigned)(KEYSPACE-1));
        atomicAdd(&tabS[k1>>1], 1u << ((k1&1)*16));
        atomicAdd(&tabD[k2>>1], 1u << ((k2&1)*16));
        __syncthreads();

        uint32_t cxS = (tabS[k1>>1] >> ((k1&1)*16)) & 0xFFFFu;
        uint32_t cyS = (tabD[k1>>1] >> ((k1&1)*16)) & 0xFFFFu;
        uint32_t cxD = (tabD[k2>>1] >> ((k2&1)*16)) & 0xFFFFu;
        uint32_t cyD = (tabS[k2>>1] >> ((k2&1)*16)) & 0xFFFFu;
        if (k1 < 8) { cxS = 0; cyS = 0; }     // id == 0 -> invalid
        if (k2 < 8) { cxD = 0; cyD = 0; }
        g_cnt[     b*LL + tid] = cxS | (cyS << 11) | ((k1 & 7u) << 22);
        g_cnt[BL + b*LL + tid] = cxD | (cyD << 11) | ((k2 & 7u) << 22);

    } else {
        // ---------------- hot-table section (deep unroll for MLP) ----------------
        int wid  = tid >> 5;
        int lane = tid & 31;
        int ce = (bid - 64)*32 + wid;         // 0..127
        int s  = ce >> 4;
        int cx = (ce >> 2) & 3;
        int cy = ce & 3;
        g_hot[ce*32 + lane] = elem_eval<16>(s, cx, cy, lane,
                                            aw1, ab1, aw2, ab2,
                                            ew1, eb1, ew2, eb2);
    }
}

// ============================================================
// Main kernel: FOUR elements per warp. One uint4 broadcast pk load,
// 4 independent L1 gathers in flight, then 4 coalesced STG.128.
// Rare cold elements: warp-collective direct MLP (warp-uniform branch).
// ============================================================
__global__ __launch_bounds__(256, 6)
void k_main(const float* __restrict__ aw1, const float* __restrict__ ab1,
            const float* __restrict__ aw2, const float* __restrict__ ab2,
            const float* __restrict__ ew1, const float* __restrict__ eb1,
            const float* __restrict__ ew2, const float* __restrict__ eb2,
            float4* __restrict__ out) {
    int lane = threadIdx.x & 31;
    int w = blockIdx.x*8 + (threadIdx.x >> 5);   // warp id
    int base = w << 2;                           // 4 elements per warp

    uint4 pks = *(const uint4*)&g_cnt[base];     // broadcast uint4 load
    uint32_t pk[4] = {pks.x, pks.y, pks.z, pks.w};
    float4 r[4];
#pragma unroll
    for (int i = 0; i < 4; ++i) {
        int cx = pk[i] & 0x7FF;
        int cy = (pk[i] >> 11) & 0x7FF;
        int s  = pk[i] >> 22;
        if ((cx | cy) < 4) {                     // warp-uniform
            r[i] = g_hot[(((s << 4) | (cx << 2) | cy) << 5) + lane];
        } else {
            r[i] = elem_direct(s, cx, cy, lane,
                               aw1, ab1, aw2, ab2, ew1, eb1, ew2, eb2);
        }
    }
#pragma unroll
    for (int i = 0; i < 4; ++i)
        out[(size_t)(base + i)*32 + lane] = r[i];
}

// ============================================================
extern "C" void kernel_launch(void* const* d_in, const int* in_sizes, int n_in,
                              void* d_out, int out_size) {
    const int*   sid = (const int*)d_in[0];
    const int*   did = (const int*)d_in[1];
    const int*   ssn = (const int*)d_in[2];
    const int*   dsn = (const int*)d_in[3];
    const float* aw1 = (const float*)d_in[5];
    const float* ab1 = (const float*)d_in[6];
    const float* aw2 = (const float*)d_in[7];
    const float* ab2 = (const float*)d_in[8];
    const float* ew1 = (const float*)d_in[9];
    const float* eb1 = (const float*)d_in[10];
    const float* ew2 = (const float*)d_in[11];
    const float* eb2 = (const float*)d_in[12];
    float4* out = (float4*)d_out;

    size_t fusedSmem = (size_t)KEYSPACE * sizeof(uint32_t);   // 64 KB
    cudaFuncSetAttribute(k_fused, cudaFuncAttributeMaxDynamicSharedMemorySize, (int)fusedSmem);

    k_fused<<<68, 1024, fusedSmem>>>(sid, did, ssn, dsn,
                                     aw1, ab1, aw2, ab2, ew1, eb1, ew2, eb2);
    k_main<<<NELEM/32, 256>>>(aw1, ab1, aw2, ab2, ew1, eb1, ew2, eb2, out);
}

// round 14
// speedup vs baseline: 1.4510x; 1.4510x over previous
#include <cuda_runtime.h>
#include <cstdint>

#define BB 64
#define LL 1024
#define SS 8
#define DD 128
#define BL (BB*LL)          // 65536
#define NELEM (2*BL)        // 131072 element-sides
#define KEYSPACE 16384      // id*8 + (snap-1), id < 2000 -> key < 16000

// ---- device scratch ----
__device__ uint32_t g_cnt[NELEM];      // hot: row idx (0..127). cold: 0x80000000|cx|cy<<11|s<<22
__device__ float4   g_hot[128*32];     // hot joint table (s<8, cx<4, cy<4), 64KB

// ============================================================
// Direct evaluation of one output row for (s, cx, cy).
// Warp-collective; lane holds float4 covering d' = 4*lane .. 4*lane+3.
// ============================================================
template <int UNROLL>
__device__ __forceinline__ float4 elem_eval(int s, int cx, int cy, int lane,
                              const float* __restrict__ aw1,
                              const float* __restrict__ ab1,
                              const float* __restrict__ aw2,
                              const float* __restrict__ ab2,
                              const float* __restrict__ ew1,
                              const float* __restrict__ eb1,
                              const float* __restrict__ ew2,
                              const float* __restrict__ eb2) {
    float fx = (float)cx, fy = (float)cy;
    float a0 = 0.f, a1 = 0.f;
#pragma unroll
    for (int m = 0; m < 4; ++m) {
        int d = lane + 32*m;
        float w = __ldg(&aw1[s*DD + d]);
        float b = __ldg(&ab1[d]);
        float h = fmaxf(fmaf(fx, w, b), 0.f) + fmaxf(fmaf(fy, w, b), 0.f);
        a0 = fmaf(h, __ldg(&aw2[2*d + 0]), a0);
        a1 = fmaf(h, __ldg(&aw2[2*d + 1]), a1);
    }
#pragma unroll
    for (int off = 16; off; off >>= 1) {
        a0 += __shfl_xor_sync(0xffffffffu, a0, off);
        a1 += __shfl_xor_sync(0xffffffffu, a1, off);
    }
    float y0 = fmaf(0.5f, a0, __ldg(&ab2[0]));
    float y1 = fmaf(0.5f, a1, __ldg(&ab2[1]));

    float4 e2 = __ldg(&((const float4*)eb2)[lane]);
    float4 acc;
    acc.x = 2.f*e2.x; acc.y = 2.f*e2.y; acc.z = 2.f*e2.z; acc.w = 2.f*e2.w;
    const float4* W2 = (const float4*)ew2;
#pragma unroll UNROLL
    for (int d = 0; d < DD; ++d) {
        float w = __ldg(&ew1[d]);
        float b = __ldg(&eb1[d]);
        float h = fmaxf(fmaf(y0, w, b), 0.f) + fmaxf(fmaf(y1, w, b), 0.f);
        float4 w2 = __ldg(&W2[d*32 + lane]);
        acc.x = fmaf(h, w2.x, acc.x);
        acc.y = fmaf(h, w2.y, acc.y);
        acc.z = fmaf(h, w2.z, acc.z);
        acc.w = fmaf(h, w2.w, acc.w);
    }
    return acc;
}

// Rare-path wrapper: noinline keeps registers out of the hot gather kernel.
__device__ __noinline__ float4 elem_direct(int s, int cx, int cy, int lane,
                              const float* __restrict__ aw1,
                              const float* __restrict__ ab1,
                              const float* __restrict__ aw2,
                              const float* __restrict__ ab2,
                              const float* __restrict__ ew1,
                              const float* __restrict__ eb1,
                              const float* __restrict__ ew2,
                              const float* __restrict__ eb2) {
    return elem_eval<4>(s, cx, cy, lane, aw1, ab1, aw2, ab2, ew1, eb1, ew2, eb2);
}

// ============================================================
// Fused kernel. Block roles by blockIdx.x:
//   [0,64)  : per-batch histogram count (64KB smem); emits decoded g_cnt
//   [64,96) : hot joint table, 4 rows per block (4 active warps) —
//             SPREAD over 32 SMs so no single SM serializes the build.
// ============================================================
__global__ __launch_bounds__(1024, 1)
void k_fused(const int* __restrict__ sid, const int* __restrict__ did,
             const int* __restrict__ ssn, const int* __restrict__ dsn,
             const float* __restrict__ aw1, const float* __restrict__ ab1,
             const float* __restrict__ aw2, const float* __restrict__ ab2,
             const float* __restrict__ ew1, const float* __restrict__ eb1,
             const float* __restrict__ ew2, const float* __restrict__ eb2) {
    extern __shared__ uint32_t smraw[];
    int bid = blockIdx.x;
    int tid = threadIdx.x;

    if (bid < 64) {
        // ---------------- count section ----------------
        uint32_t* tabS = smraw;                // KEYSPACE/2 words
        uint32_t* tabD = smraw + KEYSPACE/2;
        int b = bid;
        uint4* z = (uint4*)smraw;
#pragma unroll
        for (int i = 0; i < 4; ++i) z[tid + i*1024] = make_uint4(0,0,0,0);
        __syncthreads();

        int i = b*LL + tid;
        unsigned k1 = (unsigned)(sid[i]*8 + (ssn[i]-1));
        unsigned k2 = (unsigned)(did[i]*8 + (dsn[i]-1));
        k1 = min(k1, (unsigned)(KEYSPACE-1));
        k2 = min(k2, (unsigned)(KEYSPACE-1));
        atomicAdd(&tabS[k1>>1], 1u << ((k1&1)*16));
        atomicAdd(&tabD[k2>>1], 1u << ((k2&1)*16));
        __syncthreads();

        uint32_t cxS = (tabS[k1>>1] >> ((k1&1)*16)) & 0xFFFFu;
        uint32_t cyS = (tabD[k1>>1] >> ((k1&1)*16)) & 0xFFFFu;
        uint32_t cxD = (tabD[k2>>1] >> ((k2&1)*16)) & 0xFFFFu;
        uint32_t cyD = (tabS[k2>>1] >> ((k2&1)*16)) & 0xFFFFu;
        if (k1 < 8) { cxS = 0; cyS = 0; }     // id == 0 -> invalid
        if (k2 < 8) { cxD = 0; cyD = 0; }
        unsigned s1 = k1 & 7u, s2 = k2 & 7u;
        uint32_t v1 = ((cxS | cyS) < 4u)
                    ? ((s1 << 4) | (cxS << 2) | cyS)
                    : (0x80000000u | cxS | (cyS << 11) | (s1 << 22));
        uint32_t v2 = ((cxD | cyD) < 4u)
                    ? ((s2 << 4) | (cxD << 2) | cyD)
                    : (0x80000000u | cxD | (cyD << 11) | (s2 << 22));
        g_cnt[     b*LL + tid] = v1;
        g_cnt[BL + b*LL + tid] = v2;

    } else {
        // ---------------- hot-table section: 4 rows per block ----------------
        int wid  = tid >> 5;
        int lane = tid & 31;
        if (wid < 4) {
            int ce = (bid - 64)*4 + wid;      // 0..127
            int s  = ce >> 4;
            int cx = (ce >> 2) & 3;
            int cy = ce & 3;
            g_hot[ce*32 + lane] = elem_eval<16>(s, cx, cy, lane,
                                                aw1, ab1, aw2, ab2,
                                                ew1, eb1, ew2, eb2);
        }
    }
}

// ============================================================
// Main kernel: one warp per element. Broadcast idx load -> L1-hit
// g_hot row gather -> STG.128. Cold elements (MSB set): direct MLP.
// ============================================================
__global__ __launch_bounds__(256, 8)
void k_main(const float* __restrict__ aw1, const float* __restrict__ ab1,
            const float* __restrict__ aw2, const float* __restrict__ ab2,
            const float* __restrict__ ew1, const float* __restrict__ eb1,
            const float* __restrict__ ew2, const float* __restrict__ eb2,
            float4* __restrict__ out) {
    int lane = threadIdx.x & 31;
    int e = blockIdx.x*8 + (threadIdx.x >> 5);   // element id == warp id

    uint32_t pk = g_cnt[e];                      // broadcast: 1 wavefront/warp
    float4 r;
    if (!(pk & 0x80000000u)) {                   // hot: pk IS the row index
        r = g_hot[(pk << 5) + lane];
    } else {
        int cx = pk & 0x7FF;
        int cy = (pk >> 11) & 0x7FF;
        int s  = (pk >> 22) & 0xFF;
        r = elem_direct(s, cx, cy, lane,
                        aw1, ab1, aw2, ab2, ew1, eb1, ew2, eb2);
    }
    __stcs(&out[(size_t)e*32 + lane], r);
}

// ============================================================
extern "C" void kernel_launch(void* const* d_in, const int* in_sizes, int n_in,
                              void* d_out, int out_size) {
    const int*   sid = (const int*)d_in[0];
    const int*   did = (const int*)d_in[1];
    const int*   ssn = (const int*)d_in[2];
    const int*   dsn = (const int*)d_in[3];
    const float* aw1 = (const float*)d_in[5];
    const float* ab1 = (const float*)d_in[6];
    const float* aw2 = (const float*)d_in[7];
    const float* ab2 = (const float*)d_in[8];
    const float* ew1 = (const float*)d_in[9];
    const float* eb1 = (const float*)d_in[10];
    const float* ew2 = (const float*)d_in[11];
    const float* eb2 = (const float*)d_in[12];
    float4* out = (float4*)d_out;

    size_t fusedSmem = (size_t)KEYSPACE * sizeof(uint32_t);   // 64 KB
    cudaFuncSetAttribute(k_fused, cudaFuncAttributeMaxDynamicSharedMemorySize, (int)fusedSmem);

    k_fused<<<96, 1024, fusedSmem>>>(sid, did, ssn, dsn,
                                     aw1, ab1, aw2, ab2, ew1, eb1, ew2, eb2);
    k_main<<<NELEM/8, 256>>>(aw1, ab1, aw2, ab2, ew1, eb1, ew2, eb2, out);
}